// round 1
// baseline (speedup 1.0000x reference)
#include <cuda_runtime.h>
#include <cstdint>
#include <math.h>

#define T_TOK 4096
#define HDIM  2048
#define NEXP  16
#define FDIM  768
#define TOPK  4

// ---- scratch (device globals; no allocation allowed) ----
__device__ int   g_counts[NEXP];
__device__ int   g_tok[NEXP * T_TOK];
__device__ float g_w[NEXP * T_TOK];
__device__ int   g_eid[T_TOK * TOPK];
__device__ float g_topw[T_TOK * TOPK];
__device__ float g_act[(size_t)NEXP * T_TOK * FDIM];   // ~192 MB

// ---------------------------------------------------------------------------
// Zero output + counts
// ---------------------------------------------------------------------------
__global__ void zero_kernel(float* __restrict__ out) {
    size_t i = (size_t)blockIdx.x * blockDim.x + threadIdx.x;
    size_t n = (size_t)T_TOK * HDIM;
    size_t stride = (size_t)gridDim.x * blockDim.x;
    for (size_t j = i; j < n; j += stride) out[j] = 0.0f;
    if (i < NEXP) g_counts[i] = 0;
}

// ---------------------------------------------------------------------------
// Router: one warp per token. logits = x @ Wr^T, fp32 softmax, top-4, renorm.
// ---------------------------------------------------------------------------
__global__ void router_kernel(const float* __restrict__ x,
                              const float* __restrict__ Wr) {
    int t = blockIdx.x * blockDim.y + threadIdx.y;
    if (t >= T_TOK) return;
    int lane = threadIdx.x;
    const float* xt = x + (size_t)t * HDIM;

    float logits[NEXP];
#pragma unroll
    for (int e = 0; e < NEXP; e++) {
        const float* wr = Wr + (size_t)e * HDIM;
        float acc = 0.0f;
        for (int h = lane; h < HDIM; h += 32)
            acc += xt[h] * wr[h];
#pragma unroll
        for (int o = 16; o > 0; o >>= 1)
            acc += __shfl_xor_sync(0xffffffff, acc, o);
        logits[e] = acc;   // all lanes hold full sum
    }

    if (lane == 0) {
        float m = logits[0];
#pragma unroll
        for (int e = 1; e < NEXP; e++) m = fmaxf(m, logits[e]);
        float p[NEXP];
        float s = 0.0f;
#pragma unroll
        for (int e = 0; e < NEXP; e++) { p[e] = expf(logits[e] - m); s += p[e]; }
        float inv_s = 1.0f / s;

        bool used[NEXP];
#pragma unroll
        for (int e = 0; e < NEXP; e++) used[e] = false;

        int   ids[TOPK];
        float ws[TOPK];
        float wsum = 0.0f;
#pragma unroll
        for (int k = 0; k < TOPK; k++) {
            int bi = -1; float bv = -1.0f;
#pragma unroll
            for (int e = 0; e < NEXP; e++) {
                if (!used[e] && p[e] > bv) { bv = p[e]; bi = e; }
            }
            used[bi] = true;
            ids[k] = bi;
            ws[k]  = bv * inv_s;
            wsum  += ws[k];
        }
        float inv_w = 1.0f / wsum;
#pragma unroll
        for (int k = 0; k < TOPK; k++) {
            g_eid[t * TOPK + k]  = ids[k];
            g_topw[t * TOPK + k] = ws[k] * inv_w;
        }
    }
}

// ---------------------------------------------------------------------------
// Dispatch: build per-expert compacted token lists (atomic append).
// ---------------------------------------------------------------------------
__global__ void dispatch_kernel() {
    int i = blockIdx.x * blockDim.x + threadIdx.x;
    if (i >= T_TOK * TOPK) return;
    int e = g_eid[i];
    int pos = atomicAdd(&g_counts[e], 1);
    g_tok[e * T_TOK + pos] = i >> 2;
    g_w[e * T_TOK + pos]   = g_topw[i];
}

// ---------------------------------------------------------------------------
// GEMM1: per expert, act = silu(Xe @ Wg^T) * (Xe @ Wu^T) * route_w
// Tile 64x64, BK=16, 256 threads, 4x4 micro-tile. Gate+up share the A tile.
// grid: (T/64, F/64, E)
// ---------------------------------------------------------------------------
__global__ __launch_bounds__(256) void gemm1_kernel(const float* __restrict__ x,
                                                    const float* __restrict__ Wg,
                                                    const float* __restrict__ Wu) {
    int e   = blockIdx.z;
    int cnt = g_counts[e];
    int m0  = blockIdx.x * 64;
    if (m0 >= cnt) return;
    int n0  = blockIdx.y * 64;

    __shared__ float As[16][64];
    __shared__ float Bg[16][64];
    __shared__ float Bu[16][64];
    __shared__ int   toks[64];

    int tid = threadIdx.x;
    if (tid < 64) {
        int m = m0 + tid;
        toks[tid] = (m < cnt) ? g_tok[e * T_TOK + m] : 0;
    }
    __syncthreads();

    int r = tid >> 2;        // 0..63 (row of the 64-wide dim being loaded)
    int c = tid & 3;         // 0..3  (float4 slot in BK=16)

    const float* xa = x  + (size_t)toks[r] * HDIM + c * 4;
    const float* wg = Wg + ((size_t)e * FDIM + n0 + r) * HDIM + c * 4;
    const float* wu = Wu + ((size_t)e * FDIM + n0 + r) * HDIM + c * 4;

    int tx = tid & 15;       // n micro-tile
    int ty = tid >> 4;       // m micro-tile

    float accg[4][4] = {};
    float accu[4][4] = {};

    for (int k0 = 0; k0 < HDIM; k0 += 16) {
        float4 fa = *(const float4*)(xa + k0);
        float4 fg = *(const float4*)(wg + k0);
        float4 fu = *(const float4*)(wu + k0);
        __syncthreads();
        As[c * 4 + 0][r] = fa.x; As[c * 4 + 1][r] = fa.y;
        As[c * 4 + 2][r] = fa.z; As[c * 4 + 3][r] = fa.w;
        Bg[c * 4 + 0][r] = fg.x; Bg[c * 4 + 1][r] = fg.y;
        Bg[c * 4 + 2][r] = fg.z; Bg[c * 4 + 3][r] = fg.w;
        Bu[c * 4 + 0][r] = fu.x; Bu[c * 4 + 1][r] = fu.y;
        Bu[c * 4 + 2][r] = fu.z; Bu[c * 4 + 3][r] = fu.w;
        __syncthreads();
#pragma unroll
        for (int kk = 0; kk < 16; kk++) {
            float a[4], bg4[4], bu4[4];
            *(float4*)a   = *(const float4*)&As[kk][ty * 4];
            *(float4*)bg4 = *(const float4*)&Bg[kk][tx * 4];
            *(float4*)bu4 = *(const float4*)&Bu[kk][tx * 4];
#pragma unroll
            for (int i = 0; i < 4; i++)
#pragma unroll
                for (int j = 0; j < 4; j++) {
                    accg[i][j] += a[i] * bg4[j];
                    accu[i][j] += a[i] * bu4[j];
                }
        }
    }

#pragma unroll
    for (int i = 0; i < 4; i++) {
        int m = m0 + ty * 4 + i;
        if (m >= cnt) continue;
        float rw = g_w[e * T_TOK + m];
        float* dst = g_act + ((size_t)e * T_TOK + m) * FDIM + n0 + tx * 4;
#pragma unroll
        for (int j = 0; j < 4; j++) {
            float g = accg[i][j];
            float u = accu[i][j];
            float sg = g / (1.0f + expf(-g));   // silu
            dst[j] = sg * u * rw;
        }
    }
}

// ---------------------------------------------------------------------------
// GEMM2: per expert, out[tok] += act_rows @ Wd[e]^T   (Wd: [E, H, F])
// Tile 64x64, BK=16, K=768. grid: (T/64, H/64, E). Epilogue atomicAdd scatter.
// ---------------------------------------------------------------------------
__global__ __launch_bounds__(256) void gemm2_kernel(const float* __restrict__ Wd,
                                                    float* __restrict__ out) {
    int e   = blockIdx.z;
    int cnt = g_counts[e];
    int m0  = blockIdx.x * 64;
    if (m0 >= cnt) return;
    int n0  = blockIdx.y * 64;

    __shared__ float As[16][64];
    __shared__ float Bs[16][64];
    __shared__ int   toks[64];

    int tid = threadIdx.x;
    if (tid < 64) {
        int m = m0 + tid;
        toks[tid] = (m < cnt) ? g_tok[e * T_TOK + m] : 0;
    }
    __syncthreads();

    int r = tid >> 2;
    int c = tid & 3;

    const float* aa = g_act + ((size_t)e * T_TOK + m0 + r) * FDIM + c * 4;
    const float* wd = Wd + ((size_t)e * HDIM + n0 + r) * FDIM + c * 4;

    int tx = tid & 15;
    int ty = tid >> 4;

    float acc[4][4] = {};

    for (int k0 = 0; k0 < FDIM; k0 += 16) {
        float4 fa = *(const float4*)(aa + k0);
        float4 fb = *(const float4*)(wd + k0);
        __syncthreads();
        As[c * 4 + 0][r] = fa.x; As[c * 4 + 1][r] = fa.y;
        As[c * 4 + 2][r] = fa.z; As[c * 4 + 3][r] = fa.w;
        Bs[c * 4 + 0][r] = fb.x; Bs[c * 4 + 1][r] = fb.y;
        Bs[c * 4 + 2][r] = fb.z; Bs[c * 4 + 3][r] = fb.w;
        __syncthreads();
#pragma unroll
        for (int kk = 0; kk < 16; kk++) {
            float a[4], b[4];
            *(float4*)a = *(const float4*)&As[kk][ty * 4];
            *(float4*)b = *(const float4*)&Bs[kk][tx * 4];
#pragma unroll
            for (int i = 0; i < 4; i++)
#pragma unroll
                for (int j = 0; j < 4; j++)
                    acc[i][j] += a[i] * b[j];
        }
    }

#pragma unroll
    for (int i = 0; i < 4; i++) {
        int m = m0 + ty * 4 + i;
        if (m >= cnt) continue;
        float* dst = out + (size_t)toks[ty * 4 + i] * HDIM + n0 + tx * 4;
#pragma unroll
        for (int j = 0; j < 4; j++)
            atomicAdd(&dst[j], acc[i][j]);
    }
}

// ---------------------------------------------------------------------------
extern "C" void kernel_launch(void* const* d_in, const int* in_sizes, int n_in,
                              void* d_out, int out_size) {
    const float* x  = (const float*)d_in[0];   // [2, 2048, 2048]
    const float* Wr = (const float*)d_in[1];   // [16, 2048]
    const float* Wg = (const float*)d_in[2];   // [16, 768, 2048]
    const float* Wu = (const float*)d_in[3];   // [16, 768, 2048]
    const float* Wd = (const float*)d_in[4];   // [16, 2048, 768]
    float* out = (float*)d_out;                // [2, 2048, 2048]

    zero_kernel<<<512, 256>>>(out);

    dim3 rblk(32, 4);
    router_kernel<<<(T_TOK + 3) / 4, rblk>>>(x, Wr);

    dispatch_kernel<<<(T_TOK * TOPK + 255) / 256, 256>>>();

    dim3 g1(T_TOK / 64, FDIM / 64, NEXP);
    gemm1_kernel<<<g1, 256>>>(x, Wg, Wu);

    dim3 g2(T_TOK / 64, HDIM / 64, NEXP);
    gemm2_kernel<<<g2, 256>>>(Wd, out);
}

// round 2
// speedup vs baseline: 3.0436x; 3.0436x over previous
#include <cuda_runtime.h>
#include <cstdint>
#include <math.h>

#define T_TOK 4096
#define HDIM  2048
#define NEXP  16
#define FDIM  768
#define TOPK  4

// ---- scratch (device globals; no allocation allowed) ----
__device__ int   g_counts[NEXP];
__device__ int   g_tok[NEXP * T_TOK];
__device__ float g_w[NEXP * T_TOK];
__device__ int   g_eid[T_TOK * TOPK];
__device__ float g_topw[T_TOK * TOPK];
__device__ float g_xr[(size_t)T_TOK * HDIM];              // tf32-rounded x
__device__ float g_act[(size_t)NEXP * T_TOK * FDIM];      // tf32-rounded act

__device__ __forceinline__ float tf32r(float v) {
    uint32_t u;
    asm("cvt.rna.tf32.f32 %0, %1;" : "=r"(u) : "f"(v));
    return __uint_as_float(u);
}

#define MMA_TF32(C, A, B) \
    asm volatile("mma.sync.aligned.m16n8k8.row.col.f32.tf32.tf32.f32 " \
                 "{%0,%1,%2,%3}, {%4,%5,%6,%7}, {%8,%9}, {%0,%1,%2,%3};" \
                 : "+f"((C)[0]), "+f"((C)[1]), "+f"((C)[2]), "+f"((C)[3]) \
                 : "r"((A)[0]), "r"((A)[1]), "r"((A)[2]), "r"((A)[3]), \
                   "r"((B)[0]), "r"((B)[1]))

__device__ __forceinline__ void cp16(uint32_t smem, const void* g) {
    asm volatile("cp.async.cg.shared.global [%0], [%1], 16;" :: "r"(smem), "l"(g));
}
__device__ __forceinline__ void cp_commit() {
    asm volatile("cp.async.commit_group;");
}
template <int N>
__device__ __forceinline__ void cp_wait() {
    asm volatile("cp.async.wait_group %0;" :: "n"(N));
}

// ---------------------------------------------------------------------------
// prep: round x -> tf32 copy, zero output, zero counts
// ---------------------------------------------------------------------------
__global__ void prep_kernel(const float* __restrict__ x, float* __restrict__ out) {
    size_t i = (size_t)blockIdx.x * blockDim.x + threadIdx.x;
    size_t n = (size_t)T_TOK * HDIM;
    size_t st = (size_t)gridDim.x * blockDim.x;
    for (size_t j = i; j < n; j += st) {
        g_xr[j] = tf32r(x[j]);
        out[j] = 0.0f;
    }
    if (i < NEXP) g_counts[i] = 0;
}

// ---------------------------------------------------------------------------
// Router: one warp per token (fp32 exact)
// ---------------------------------------------------------------------------
__global__ void router_kernel(const float* __restrict__ x,
                              const float* __restrict__ Wr) {
    int t = blockIdx.x * blockDim.y + threadIdx.y;
    if (t >= T_TOK) return;
    int lane = threadIdx.x;
    const float* xt = x + (size_t)t * HDIM;

    float logits[NEXP];
#pragma unroll
    for (int e = 0; e < NEXP; e++) {
        const float* wr = Wr + (size_t)e * HDIM;
        float acc = 0.0f;
        for (int h = lane; h < HDIM; h += 32)
            acc += xt[h] * wr[h];
#pragma unroll
        for (int o = 16; o > 0; o >>= 1)
            acc += __shfl_xor_sync(0xffffffff, acc, o);
        logits[e] = acc;
    }

    if (lane == 0) {
        float m = logits[0];
#pragma unroll
        for (int e = 1; e < NEXP; e++) m = fmaxf(m, logits[e]);
        float p[NEXP];
        float s = 0.0f;
#pragma unroll
        for (int e = 0; e < NEXP; e++) { p[e] = expf(logits[e] - m); s += p[e]; }
        float inv_s = 1.0f / s;

        bool used[NEXP];
#pragma unroll
        for (int e = 0; e < NEXP; e++) used[e] = false;

        int ids[TOPK]; float ws[TOPK]; float wsum = 0.0f;
#pragma unroll
        for (int k = 0; k < TOPK; k++) {
            int bi = -1; float bv = -1.0f;
#pragma unroll
            for (int e = 0; e < NEXP; e++)
                if (!used[e] && p[e] > bv) { bv = p[e]; bi = e; }
            used[bi] = true;
            ids[k] = bi;
            ws[k]  = bv * inv_s;
            wsum  += ws[k];
        }
        float inv_w = 1.0f / wsum;
#pragma unroll
        for (int k = 0; k < TOPK; k++) {
            g_eid[t * TOPK + k]  = ids[k];
            g_topw[t * TOPK + k] = ws[k] * inv_w;
        }
    }
}

__global__ void dispatch_kernel() {
    int i = blockIdx.x * blockDim.x + threadIdx.x;
    if (i >= T_TOK * TOPK) return;
    int e = g_eid[i];
    int pos = atomicAdd(&g_counts[e], 1);
    g_tok[e * T_TOK + pos] = i >> 2;
    g_w[e * T_TOK + pos]   = g_topw[i];
}

// ---------------------------------------------------------------------------
// GEMM1 (tf32 mma): act = tf32(silu(Xe Wg^T) * (Xe Wu^T) * rw)
// BM=128, BN=64, BK=16. 8 warps: warp (wm 0..3, wn 0..1) -> 32x32 tile each.
// grid (T/128, F/64, E)
// ---------------------------------------------------------------------------
#define BM 128
#define BN 64
#define BK 16
#define APAD 20

__global__ __launch_bounds__(256) void gemm1_kernel(const float* __restrict__ Wg,
                                                    const float* __restrict__ Wu) {
    int e = blockIdx.z;
    int cnt = g_counts[e];
    int m0 = blockIdx.x * BM;
    if (m0 >= cnt) return;
    int n0 = blockIdx.y * BN;

    __shared__ float As[2][BM][APAD];
    __shared__ float Bgs[2][BN][APAD];
    __shared__ float Bus[2][BN][APAD];
    __shared__ int   toks[BM];

    int tid = threadIdx.x;
    if (tid < BM) toks[tid] = (m0 + tid < cnt) ? g_tok[e * T_TOK + m0 + tid] : 0;
    __syncthreads();

    int lr = tid >> 2;            // 0..63
    int lc = (tid & 3) * 4;       // 0,4,8,12
    const float* a_src0 = g_xr + (size_t)toks[lr] * HDIM + lc;
    const float* a_src1 = g_xr + (size_t)toks[lr + 64] * HDIM + lc;
    const float* bg_src = Wg + ((size_t)e * FDIM + n0 + lr) * HDIM + lc;
    const float* bu_src = Wu + ((size_t)e * FDIM + n0 + lr) * HDIM + lc;

    uint32_t sa0 = (uint32_t)__cvta_generic_to_shared(&As[0][lr][lc]);
    uint32_t sa1 = (uint32_t)__cvta_generic_to_shared(&As[0][lr + 64][lc]);
    const uint32_t stageA = sizeof(float) * BM * APAD;

    // prologue: A tile0 via cp.async, B tile0 into regs
    cp16(sa0, a_src0);
    cp16(sa1, a_src1);
    cp_commit();
    float4 bg_reg = *(const float4*)bg_src;
    float4 bu_reg = *(const float4*)bu_src;

    int warp = tid >> 5, lane = tid & 31;
    int wm = warp & 3, wn = warp >> 2;
    int qr = lane >> 2, qc = lane & 3;

    float accg[2][4][4] = {}, accu[2][4][4] = {};

    const int NIT = HDIM / BK;    // 128
    for (int it = 0; it < NIT; ++it) {
        int cur = it & 1, nxt = cur ^ 1;
        __syncthreads();          // all warps done computing previous tile

        float4 bg_n, bu_n;
        bool has_next = (it + 1 < NIT);
        if (has_next) {
            int k0 = (it + 1) * BK;
            cp16(sa0 + nxt * stageA, a_src0 + k0);
            cp16(sa1 + nxt * stageA, a_src1 + k0);
            cp_commit();
            bg_n = *(const float4*)(bg_src + k0);
            bu_n = *(const float4*)(bu_src + k0);
        }
        // store current B tile (tf32-rounded)
        Bgs[cur][lr][lc + 0] = tf32r(bg_reg.x);
        Bgs[cur][lr][lc + 1] = tf32r(bg_reg.y);
        Bgs[cur][lr][lc + 2] = tf32r(bg_reg.z);
        Bgs[cur][lr][lc + 3] = tf32r(bg_reg.w);
        Bus[cur][lr][lc + 0] = tf32r(bu_reg.x);
        Bus[cur][lr][lc + 1] = tf32r(bu_reg.y);
        Bus[cur][lr][lc + 2] = tf32r(bu_reg.z);
        Bus[cur][lr][lc + 3] = tf32r(bu_reg.w);

        if (has_next) cp_wait<1>(); else cp_wait<0>();
        __syncthreads();

#pragma unroll
        for (int ks = 0; ks < 2; ++ks) {
            int kb = ks * 8;
            uint32_t a[2][4];
#pragma unroll
            for (int mi = 0; mi < 2; ++mi) {
                int row = wm * 32 + mi * 16 + qr;
                a[mi][0] = __float_as_uint(As[cur][row][kb + qc]);
                a[mi][1] = __float_as_uint(As[cur][row + 8][kb + qc]);
                a[mi][2] = __float_as_uint(As[cur][row][kb + qc + 4]);
                a[mi][3] = __float_as_uint(As[cur][row + 8][kb + qc + 4]);
            }
#pragma unroll
            for (int ni = 0; ni < 4; ++ni) {
                int col = wn * 32 + ni * 8 + qr;
                uint32_t bg[2], bu[2];
                bg[0] = __float_as_uint(Bgs[cur][col][kb + qc]);
                bg[1] = __float_as_uint(Bgs[cur][col][kb + qc + 4]);
                bu[0] = __float_as_uint(Bus[cur][col][kb + qc]);
                bu[1] = __float_as_uint(Bus[cur][col][kb + qc + 4]);
#pragma unroll
                for (int mi = 0; mi < 2; ++mi) {
                    MMA_TF32(accg[mi][ni], a[mi], bg);
                    MMA_TF32(accu[mi][ni], a[mi], bu);
                }
            }
        }
        bg_reg = bg_n;
        bu_reg = bu_n;
    }

    // epilogue: silu(g)*u*rw, tf32-rounded, -> g_act (compacted rows)
#pragma unroll
    for (int mi = 0; mi < 2; ++mi) {
#pragma unroll
        for (int rh = 0; rh < 2; ++rh) {
            int ml = wm * 32 + mi * 16 + qr + rh * 8;
            int m  = m0 + ml;
            if (m < cnt) {
                float rw = g_w[e * T_TOK + m];
                float* dst = g_act + ((size_t)e * T_TOK + m) * FDIM
                           + n0 + wn * 32 + qc * 2;
#pragma unroll
                for (int ni = 0; ni < 4; ++ni) {
                    float g0 = accg[mi][ni][rh * 2 + 0];
                    float g1 = accg[mi][ni][rh * 2 + 1];
                    float u0 = accu[mi][ni][rh * 2 + 0];
                    float u1 = accu[mi][ni][rh * 2 + 1];
                    float v0 = tf32r(g0 / (1.0f + expf(-g0)) * u0 * rw);
                    float v1 = tf32r(g1 / (1.0f + expf(-g1)) * u1 * rw);
                    *(float2*)(dst + ni * 8) = make_float2(v0, v1);
                }
            }
        }
    }
}

// ---------------------------------------------------------------------------
// GEMM2 (tf32 mma): out[tok] += act @ Wd^T. K=768. grid (T/128, H/64, E).
// ---------------------------------------------------------------------------
__global__ __launch_bounds__(256) void gemm2_kernel(const float* __restrict__ Wd,
                                                    float* __restrict__ out) {
    int e = blockIdx.z;
    int cnt = g_counts[e];
    int m0 = blockIdx.x * BM;
    if (m0 >= cnt) return;
    int n0 = blockIdx.y * BN;

    __shared__ float As[2][BM][APAD];
    __shared__ float Bs[2][BN][APAD];
    __shared__ int   toks[BM];

    int tid = threadIdx.x;
    if (tid < BM) toks[tid] = (m0 + tid < cnt) ? g_tok[e * T_TOK + m0 + tid] : 0;
    __syncthreads();

    int lr = tid >> 2;
    int lc = (tid & 3) * 4;
    const float* a_src0 = g_act + ((size_t)e * T_TOK + m0 + lr) * FDIM + lc;
    const float* a_src1 = g_act + ((size_t)e * T_TOK + m0 + lr + 64) * FDIM + lc;
    const float* b_src  = Wd + ((size_t)e * HDIM + n0 + lr) * FDIM + lc;

    uint32_t sa0 = (uint32_t)__cvta_generic_to_shared(&As[0][lr][lc]);
    uint32_t sa1 = (uint32_t)__cvta_generic_to_shared(&As[0][lr + 64][lc]);
    const uint32_t stageA = sizeof(float) * BM * APAD;

    cp16(sa0, a_src0);
    cp16(sa1, a_src1);
    cp_commit();
    float4 b_reg = *(const float4*)b_src;

    int warp = tid >> 5, lane = tid & 31;
    int wm = warp & 3, wn = warp >> 2;
    int qr = lane >> 2, qc = lane & 3;

    float acc[2][4][4] = {};

    const int NIT = FDIM / BK;    // 48
    for (int it = 0; it < NIT; ++it) {
        int cur = it & 1, nxt = cur ^ 1;
        __syncthreads();

        float4 b_n;
        bool has_next = (it + 1 < NIT);
        if (has_next) {
            int k0 = (it + 1) * BK;
            cp16(sa0 + nxt * stageA, a_src0 + k0);
            cp16(sa1 + nxt * stageA, a_src1 + k0);
            cp_commit();
            b_n = *(const float4*)(b_src + k0);
        }
        Bs[cur][lr][lc + 0] = tf32r(b_reg.x);
        Bs[cur][lr][lc + 1] = tf32r(b_reg.y);
        Bs[cur][lr][lc + 2] = tf32r(b_reg.z);
        Bs[cur][lr][lc + 3] = tf32r(b_reg.w);

        if (has_next) cp_wait<1>(); else cp_wait<0>();
        __syncthreads();

#pragma unroll
        for (int ks = 0; ks < 2; ++ks) {
            int kb = ks * 8;
            uint32_t a[2][4];
#pragma unroll
            for (int mi = 0; mi < 2; ++mi) {
                int row = wm * 32 + mi * 16 + qr;
                a[mi][0] = __float_as_uint(As[cur][row][kb + qc]);
                a[mi][1] = __float_as_uint(As[cur][row + 8][kb + qc]);
                a[mi][2] = __float_as_uint(As[cur][row][kb + qc + 4]);
                a[mi][3] = __float_as_uint(As[cur][row + 8][kb + qc + 4]);
            }
#pragma unroll
            for (int ni = 0; ni < 4; ++ni) {
                int col = wn * 32 + ni * 8 + qr;
                uint32_t b[2];
                b[0] = __float_as_uint(Bs[cur][col][kb + qc]);
                b[1] = __float_as_uint(Bs[cur][col][kb + qc + 4]);
#pragma unroll
                for (int mi = 0; mi < 2; ++mi)
                    MMA_TF32(acc[mi][ni], a[mi], b);
            }
        }
        b_reg = b_n;
    }

    // epilogue: scatter-add into out
#pragma unroll
    for (int mi = 0; mi < 2; ++mi) {
#pragma unroll
        for (int rh = 0; rh < 2; ++rh) {
            int ml = wm * 32 + mi * 16 + qr + rh * 8;
            int m  = m0 + ml;
            if (m < cnt) {
                float* dst = out + (size_t)toks[ml] * HDIM + n0 + wn * 32 + qc * 2;
#pragma unroll
                for (int ni = 0; ni < 4; ++ni) {
                    atomicAdd(dst + ni * 8 + 0, acc[mi][ni][rh * 2 + 0]);
                    atomicAdd(dst + ni * 8 + 1, acc[mi][ni][rh * 2 + 1]);
                }
            }
        }
    }
}

// ---------------------------------------------------------------------------
extern "C" void kernel_launch(void* const* d_in, const int* in_sizes, int n_in,
                              void* d_out, int out_size) {
    const float* x  = (const float*)d_in[0];
    const float* Wr = (const float*)d_in[1];
    const float* Wg = (const float*)d_in[2];
    const float* Wu = (const float*)d_in[3];
    const float* Wd = (const float*)d_in[4];
    float* out = (float*)d_out;

    prep_kernel<<<1024, 256>>>(x, out);

    dim3 rblk(32, 4);
    router_kernel<<<(T_TOK + 3) / 4, rblk>>>(x, Wr);

    dispatch_kernel<<<(T_TOK * TOPK + 255) / 256, 256>>>();

    dim3 g1(T_TOK / BM, FDIM / BN, NEXP);
    gemm1_kernel<<<g1, 256>>>(Wg, Wu);

    dim3 g2(T_TOK / BM, HDIM / BN, NEXP);
    gemm2_kernel<<<g2, 256>>>(Wd, out);
}